// round 14
// baseline (speedup 1.0000x reference)
#include <cuda_runtime.h>
#include <cuda_bf16.h>
#include <cstddef>

typedef unsigned long long u64;

// Problem constants
#define BB 16
#define NN 4096
#define DD 64
#define SS 1024          // NPOINT
#define KK 32            // NSAMPLE
#define R2 0.04f         // RADIUS^2
#define NT 524288u       // B*S*K
#define INV_NT (1.0f/524288.0f)
#define BN_EPS 1e-5f
#define MLP_GRID 296     // 2 CTAs/SM * 148 SMs

#define FMA_F32X2(d, a, b, c) \
    asm("fma.rn.f32x2 %0, %1, %2, %3;" : "=l"(d) : "l"(a), "l"(b), "l"(c))
#define ADD_F32X2(d, a, b) \
    asm("add.rn.f32x2 %0, %1, %2;" : "=l"(d) : "l"(a), "l"(b))
#define SUB_F32X2(d, a, b) \
    asm("sub.rn.f32x2 %0, %1, %2;" : "=l"(d) : "l"(a), "l"(b))
#define MUL_F32X2(d, a, b) \
    asm("mul.rn.f32x2 %0, %1, %2;" : "=l"(d) : "l"(a), "l"(b))
#define PACK_F32X2(out, lo, hi) \
    asm("mov.b64 %0, {%1, %2};" : "=l"(out) : "f"(lo), "f"(hi))
#define PACK_DUP_F32X2(out, w) \
    asm("mov.b64 %0, {%1, %1};" : "=l"(out) : "r"(__float_as_uint(w)))
#define UNPACK_F32X2(lo, hi, in) \
    asm("mov.b64 {%0, %1}, %2;" : "=f"(lo), "=f"(hi) : "l"(in))

// ---------------- scratch (device globals) ----------------------------------
__device__ float g_feat[67u * NT];     // layer-0 input, channel-major [c][n]
__device__ float g_h0[64u * NT];       // raw h of layer 0
__device__ float g_h1[64u * NT];       // raw h of layer 1
__device__ float g_hmax[128u * 16384]; // per-(bs,o) max of raw h2
__device__ float g_hmin[128u * 16384]; // per-(bs,o) min of raw h2
__device__ float g_sum[3 * 128];
__device__ float g_sqs[3 * 128];

__global__ void zero_stats_kernel() {
    int t = threadIdx.x;
    if (t < 384) { g_sum[t] = 0.f; g_sqs[t] = 0.f; }
}

// ---------------- farthest point sampling (R12, unchanged) -------------------
__global__ __launch_bounds__(512, 1)
void fps_kernel(const float* __restrict__ xyz, float* __restrict__ out_newxyz) {
    extern __shared__ float fsm[];
    float* xs = fsm;
    float* ys = fsm + 4096;
    float* zs = fsm + 8192;
    unsigned* rv = (unsigned*)(fsm + 12288);   // [2][16]
    unsigned* ri = (unsigned*)(fsm + 12320);   // [2][16]

    const int b = blockIdx.x, tid = threadIdx.x;
    const int lane = tid & 31, wid = tid >> 5;

    const float* base = xyz + (size_t)b * NN * 3;
    for (int i = tid; i < NN; i += 512) {
        xs[i] = base[i * 3 + 0];
        ys[i] = base[i * 3 + 1];
        zs[i] = base[i * 3 + 2];
    }
    __syncthreads();

    u64 ppx[4], ppy[4], ppz[4];
    float dist[8];
#pragma unroll
    for (int h = 0; h < 4; h++) {
        int i0 = tid + (2 * h) * 512;
        int i1 = tid + (2 * h + 1) * 512;
        PACK_F32X2(ppx[h], xs[i0], xs[i1]);
        PACK_F32X2(ppy[h], ys[i0], ys[i1]);
        PACK_F32X2(ppz[h], zs[i0], zs[i1]);
        dist[2 * h] = 1e10f; dist[2 * h + 1] = 1e10f;
    }

    int cur = 0;
    for (int s = 0; s < SS; s++) {
        if (tid == 0) {
            float* o = out_newxyz + ((size_t)b * SS + s) * 3;
            o[0] = xs[cur]; o[1] = ys[cur]; o[2] = zs[cur];
        }
        u64 cx2, cy2, cz2;
        PACK_DUP_F32X2(cx2, xs[cur]);
        PACK_DUP_F32X2(cy2, ys[cur]);
        PACK_DUP_F32X2(cz2, zs[cur]);

        float bv = -1.0f;
#pragma unroll
        for (int h = 0; h < 4; h++) {
            u64 dx2, dy2, dz2, m1, m2, s1, m3, d2;
            SUB_F32X2(dx2, ppx[h], cx2);
            SUB_F32X2(dy2, ppy[h], cy2);
            SUB_F32X2(dz2, ppz[h], cz2);
            MUL_F32X2(m1, dx2, dx2);
            MUL_F32X2(m2, dy2, dy2);
            ADD_F32X2(s1, m1, m2);
            MUL_F32X2(m3, dz2, dz2);
            ADD_F32X2(d2, s1, m3);
            float d0, d1;
            UNPACK_F32X2(d0, d1, d2);
            float nd0 = fminf(dist[2 * h], d0);
            float nd1 = fminf(dist[2 * h + 1], d1);
            dist[2 * h] = nd0; dist[2 * h + 1] = nd1;
            bv = fmaxf(bv, fmaxf(nd0, nd1));
        }

        unsigned mybits = __float_as_uint(bv);
        unsigned wm = __reduce_max_sync(0xffffffffu, mybits);
        unsigned cand = 0xffffffffu;
        if (mybits == wm) {
#pragma unroll
            for (int t = 7; t >= 0; t--)
                if (dist[t] == bv) cand = (unsigned)(tid + t * 512);
        }
        unsigned wi = __reduce_min_sync(0xffffffffu, cand);
        unsigned* rvp = rv + (s & 1) * 16;
        unsigned* rip = ri + (s & 1) * 16;
        if (lane == 0) { rvp[wid] = wm; rip[wid] = wi; }
        __syncthreads();
        unsigned v  = rvp[lane & 15];
        unsigned ix = rip[lane & 15];
        unsigned gm = __reduce_max_sync(0xffffffffu, v);
        unsigned c2 = (v == gm) ? ix : 0xffffffffu;
        cur = (int)__reduce_min_sync(0xffffffffu, c2);
    }
}

// ---------------- ball query + gather + concat -> g_feat ---------------------
// 1024 threads / 32 query-warps per block, 32 blocks per batch (4x less
// redundant xyz staging than the 256-thread version).
__global__ __launch_bounds__(1024, 1)
void group_kernel(const float* __restrict__ xyz,
                  const float* __restrict__ points,
                  const float* __restrict__ newxyz) {
    extern __shared__ float gsm[];
    float* xs = gsm;
    float* ys = gsm + 4096;
    float* zs = gsm + 8192;
    float* pn = gsm + 12288;
    int* slots = (int*)(gsm + 16384);       // 32 warps * 32 ints

    const int tid = threadIdx.x;
    const int lane = tid & 31, wid = tid >> 5;
    const int b = blockIdx.x >> 5;          // 32 blocks per batch

    const float* base = xyz + (size_t)b * NN * 3;
    for (int i = tid; i < NN; i += 1024) {
        float x = base[i * 3 + 0], y = base[i * 3 + 1], z = base[i * 3 + 2];
        xs[i] = x; ys[i] = y; zs[i] = z;
        pn[i] = __fadd_rn(__fadd_rn(__fmul_rn(x, x), __fmul_rn(y, y)),
                          __fmul_rn(z, z));
    }
    __syncthreads();

    const int s = (blockIdx.x & 31) * 32 + wid;     // query within batch
    const float* q = newxyz + ((size_t)b * SS + s) * 3;
    const float nx = q[0], ny = q[1], nz = q[2];
    const float qn = __fadd_rn(__fadd_rn(__fmul_rn(nx, nx), __fmul_rn(ny, ny)),
                               __fmul_rn(nz, nz));

    int* msl = slots + wid * 32;
    int cnt = 0;
    for (int c = 0; c < 128 && cnt < 32; c++) {
        int i = c * 32 + lane;
        float dot = __fadd_rn(__fadd_rn(__fmul_rn(nx, xs[i]), __fmul_rn(ny, ys[i])),
                              __fmul_rn(nz, zs[i]));
        float d = __fadd_rn(__fadd_rn(__fmul_rn(-2.0f, dot), qn), pn[i]);
        bool in = !(d > R2);
        unsigned m = __ballot_sync(0xffffffffu, in);
        if (in) {
            int pos = cnt + __popc(m & ((1u << lane) - 1u));
            if (pos < 32) msl[pos] = i;
        }
        cnt += __popc(m);
    }
    __syncwarp();
    int cc = cnt < 32 ? cnt : 32;
    int my = msl[lane < cc ? lane : 0];

    const unsigned n = ((unsigned)(b * SS + s)) * KK + lane;
    g_feat[0u * NT + n] = xs[my] - nx;
    g_feat[1u * NT + n] = ys[my] - ny;
    g_feat[2u * NT + n] = zs[my] - nz;
    const float4* pr = (const float4*)(points + ((size_t)(b * NN + my)) * DD);
#pragma unroll
    for (int j = 0; j < 16; j++) {
        float4 v = pr[j];
        g_feat[(size_t)(3 + 4 * j + 0) * NT + n] = v.x;
        g_feat[(size_t)(3 + 4 * j + 1) * NT + n] = v.y;
        g_feat[(size_t)(3 + 4 * j + 2) * NT + n] = v.z;
        g_feat[(size_t)(3 + 4 * j + 3) * NT + n] = v.w;
    }
}

// ---------------- persistent fused GEMM via packed f32x2 FFMA ----------------
// 8x8 microtile, 256 threads, 2 CTAs/SM. W pre-duplicated in smem as u64
// {w,w} pairs (no per-iter MOV packs); stats flushed once per CTA.
template <int CIN, int COUT, int NTILE, bool BN, bool LAST>
__global__ __launch_bounds__(256, 2)
void mlp_kernel(const float* __restrict__ in,
                const float* __restrict__ w,
                const float* __restrict__ bias,
                const float* __restrict__ sum_in,
                const float* __restrict__ sqs_in,
                const float* __restrict__ gamma,
                const float* __restrict__ beta,
                float* __restrict__ out,
                float* __restrict__ sum_out,
                float* __restrict__ sqs_out,
                float* __restrict__ hmax,
                float* __restrict__ hmin) {
    constexpr int TNG = NTILE / 8;
    constexpr int NTL = (int)(NT / NTILE);
    extern __shared__ float sm[];
    u64*   wt2 = (u64*)sm;                  // [CIN][COUT] duplicated pairs
    float* xt  = (float*)(wt2 + CIN * COUT);// [CIN][NTILE]
    float* scs = xt + CIN * NTILE;          // [CIN]
    float* shs = scs + CIN;                 // [CIN]

    const int tid = threadIdx.x;
    const int tn = tid % TNG;
    const int to = tid / TNG;

    // ---- once-per-CTA staging ----
    if (BN && tid < CIN) {
        float m = sum_in[tid] * INV_NT;
        float v = sqs_in[tid] * INV_NT - m * m;
        float sc = gamma[tid] / sqrtf(v + BN_EPS);
        scs[tid] = sc;
        shs[tid] = beta[tid] - m * sc;
    }
    for (int i = tid; i < CIN * COUT; i += 256) {
        int o = i / CIN, c = i % CIN;
        unsigned bits = __float_as_uint(w[i]);
        wt2[c * COUT + o] = ((u64)bits << 32) | (u64)bits;
    }
    float bv8[8];
#pragma unroll
    for (int a = 0; a < 8; a++) bv8[a] = bias[to * 8 + a];

    float s_acc[8], s2_acc[8];
#pragma unroll
    for (int a = 0; a < 8; a++) { s_acc[a] = 0.f; s2_acc[a] = 0.f; }

    const u64* wrow = wt2 + to * 8;

    // ---- persistent tile loop ----
    for (int tile = blockIdx.x; tile < NTL; tile += MLP_GRID) {
        __syncthreads();   // fence xt reuse (also orders first-tile staging)
        const unsigned nb = (unsigned)tile * (unsigned)NTILE;
        for (int i = tid; i < CIN * NTILE; i += 256) {
            int c = i / NTILE, nn = i % NTILE;
            float v = in[(size_t)c * NT + nb + nn];
            if (BN) v = fmaxf(__fmaf_rn(v, scs[c], shs[c]), 0.0f);
            xt[i] = v;
        }
        __syncthreads();

        u64 acc2[8][4];
#pragma unroll
        for (int a = 0; a < 8; a++)
#pragma unroll
            for (int j = 0; j < 4; j++) acc2[a][j] = 0ull;

#pragma unroll 2
        for (int c = 0; c < CIN; c++) {
            const ulonglong2* xp = (const ulonglong2*)&xt[c * NTILE + tn * 8];
            ulonglong2 x01 = xp[0], x23 = xp[1];
            u64 xr2[4] = {x01.x, x01.y, x23.x, x23.y};
            const ulonglong2* wp2 = (const ulonglong2*)&wrow[c * COUT];
            ulonglong2 w01 = wp2[0], w23 = wp2[1], w45 = wp2[2], w67 = wp2[3];
            u64 wp[8] = {w01.x, w01.y, w23.x, w23.y, w45.x, w45.y, w67.x, w67.y};
#pragma unroll
            for (int a = 0; a < 8; a++)
#pragma unroll
                for (int j = 0; j < 4; j++)
                    FMA_F32X2(acc2[a][j], wp[a], xr2[j], acc2[a][j]);
        }

        const unsigned n0 = nb + tn * 8;
#pragma unroll
        for (int a = 0; a < 8; a++) {
            int o = to * 8 + a;
            float r[8];
#pragma unroll
            for (int j = 0; j < 4; j++)
                UNPACK_F32X2(r[2 * j], r[2 * j + 1], acc2[a][j]);
            float s = 0.f, s2 = 0.f;
#pragma unroll
            for (int j = 0; j < 8; j++) {
                r[j] = r[j] + bv8[a];
                s += r[j];
                s2 = __fmaf_rn(r[j], r[j], s2);
            }
            s_acc[a] += s;
            s2_acc[a] += s2;
            if (!LAST) {
                float4* op = (float4*)&out[(size_t)o * NT + n0];
                op[0] = make_float4(r[0], r[1], r[2], r[3]);
                op[1] = make_float4(r[4], r[5], r[6], r[7]);
            }
            if (LAST) {
                float mx = r[0], mn = r[0];
#pragma unroll
                for (int j = 1; j < 8; j++) { mx = fmaxf(mx, r[j]); mn = fminf(mn, r[j]); }
                mx = fmaxf(mx, __shfl_xor_sync(0xffffffffu, mx, 1));
                mx = fmaxf(mx, __shfl_xor_sync(0xffffffffu, mx, 2));
                mn = fminf(mn, __shfl_xor_sync(0xffffffffu, mn, 1));
                mn = fminf(mn, __shfl_xor_sync(0xffffffffu, mn, 2));
                if ((tn & 3) == 0) {
                    unsigned bs = nb / KK + (tn >> 2);
                    hmax[(size_t)bs * COUT + o] = mx;
                    hmin[(size_t)bs * COUT + o] = mn;
                }
            }
        }
    }

    // ---- stats flush: once per CTA ----
#pragma unroll
    for (int a = 0; a < 8; a++) {
        float s = s_acc[a], s2 = s2_acc[a];
#pragma unroll
        for (int m = 1; m < TNG; m <<= 1) {
            s  += __shfl_xor_sync(0xffffffffu, s,  m);
            s2 += __shfl_xor_sync(0xffffffffu, s2, m);
        }
        if (tn == 0) {
            atomicAdd(&sum_out[to * 8 + a], s);
            atomicAdd(&sqs_out[to * 8 + a], s2);
        }
    }
}

// ---------------- final BN + ReLU applied to pooled max/min ------------------
__global__ void pool_kernel(const float* __restrict__ hmax,
                            const float* __restrict__ hmin,
                            const float* __restrict__ sum_in,
                            const float* __restrict__ sqs_in,
                            const float* __restrict__ gamma,
                            const float* __restrict__ beta,
                            float* __restrict__ out) {
    unsigned idx = blockIdx.x * 256u + threadIdx.x;
    int o = idx & 127;
    float m = sum_in[o] * INV_NT;
    float v = sqs_in[o] * INV_NT - m * m;
    float sc = gamma[o] / sqrtf(v + BN_EPS);
    float sh = beta[o] - m * sc;
    float r = (sc >= 0.0f) ? hmax[idx] : hmin[idx];
    out[(size_t)BB * SS * 3 + idx] = fmaxf(__fmaf_rn(r, sc, sh), 0.0f);
}

// ---------------- host launch ----------------------------------------------
extern "C" void kernel_launch(void* const* d_in, const int* in_sizes, int n_in,
                              void* d_out, int out_size) {
    const float* xyz    = (const float*)d_in[0];
    const float* points = (const float*)d_in[1];
    const float* w0 = (const float*)d_in[2];
    const float* b0 = (const float*)d_in[3];
    const float* g0 = (const float*)d_in[4];
    const float* be0 = (const float*)d_in[5];
    const float* w1 = (const float*)d_in[6];
    const float* b1 = (const float*)d_in[7];
    const float* g1 = (const float*)d_in[8];
    const float* be1 = (const float*)d_in[9];
    const float* w2 = (const float*)d_in[10];
    const float* b2 = (const float*)d_in[11];
    const float* g2 = (const float*)d_in[12];
    const float* be2 = (const float*)d_in[13];
    float* out = (float*)d_out;

    void *featp, *h0p, *h1p, *hmaxp, *hminp, *sump, *sqsp;
    cudaGetSymbolAddress(&featp, g_feat);
    cudaGetSymbolAddress(&h0p, g_h0);
    cudaGetSymbolAddress(&h1p, g_h1);
    cudaGetSymbolAddress(&hmaxp, g_hmax);
    cudaGetSymbolAddress(&hminp, g_hmin);
    cudaGetSymbolAddress(&sump, g_sum);
    cudaGetSymbolAddress(&sqsp, g_sqs);
    float* sum0 = (float*)sump;        float* sqs0 = (float*)sqsp;
    float* sum1 = sum0 + 128;          float* sqs1 = sqs0 + 128;
    float* sum2 = sum0 + 256;          float* sqs2 = sqs0 + 256;

    const int FPS_SMEM = (12288 + 64) * 4;
    const int GRP_SMEM = (16384 + 1024) * 4;
    const int S1 = 67 * 64 * 8 + 67 * 256 * 4 + 2 * 67 * 4;   // 103448
    const int S2 = 64 * 64 * 8 + 64 * 256 * 4 + 2 * 64 * 4;   //  98816
    const int S3 = 64 * 128 * 8 + 64 * 128 * 4 + 2 * 64 * 4;  //  98816

    cudaFuncSetAttribute(fps_kernel, cudaFuncAttributeMaxDynamicSharedMemorySize, FPS_SMEM);
    cudaFuncSetAttribute(group_kernel, cudaFuncAttributeMaxDynamicSharedMemorySize, GRP_SMEM);
    cudaFuncSetAttribute(mlp_kernel<67, 64, 256, false, false>, cudaFuncAttributeMaxDynamicSharedMemorySize, S1);
    cudaFuncSetAttribute(mlp_kernel<64, 64, 256, true, false>, cudaFuncAttributeMaxDynamicSharedMemorySize, S2);
    cudaFuncSetAttribute(mlp_kernel<64, 128, 128, true, true>, cudaFuncAttributeMaxDynamicSharedMemorySize, S3);

    zero_stats_kernel<<<1, 384>>>();
    fps_kernel<<<BB, 512, FPS_SMEM>>>(xyz, out);
    group_kernel<<<BB * 32, 1024, GRP_SMEM>>>(xyz, points, out);

    mlp_kernel<67, 64, 256, false, false><<<MLP_GRID, 256, S1>>>(
        (const float*)featp, w0, b0, nullptr, nullptr, nullptr, nullptr,
        (float*)h0p, sum0, sqs0, nullptr, nullptr);
    mlp_kernel<64, 64, 256, true, false><<<MLP_GRID, 256, S2>>>(
        (const float*)h0p, w1, b1, sum0, sqs0, g0, be0,
        (float*)h1p, sum1, sqs1, nullptr, nullptr);
    mlp_kernel<64, 128, 128, true, true><<<MLP_GRID, 256, S3>>>(
        (const float*)h1p, w2, b2, sum1, sqs1, g1, be1,
        nullptr, sum2, sqs2, (float*)hmaxp, (float*)hminp);

    pool_kernel<<<(BB * SS * 128) / 256, 256>>>(
        (const float*)hmaxp, (const float*)hminp, sum2, sqs2, g2, be2, out);
}

// round 15
// speedup vs baseline: 1.0411x; 1.0411x over previous
#include <cuda_runtime.h>
#include <cuda_bf16.h>
#include <cstddef>

typedef unsigned long long u64;

// Problem constants
#define BB 16
#define NN 4096
#define DD 64
#define SS 1024          // NPOINT
#define KK 32            // NSAMPLE
#define R2 0.04f         // RADIUS^2
#define NT 524288u       // B*S*K
#define INV_NT (1.0f/524288.0f)
#define BN_EPS 1e-5f
#define MLP_GRID 296     // 2 CTAs/SM * 148 SMs

#define FMA_F32X2(d, a, b, c) \
    asm("fma.rn.f32x2 %0, %1, %2, %3;" : "=l"(d) : "l"(a), "l"(b), "l"(c))
#define ADD_F32X2(d, a, b) \
    asm("add.rn.f32x2 %0, %1, %2;" : "=l"(d) : "l"(a), "l"(b))
#define SUB_F32X2(d, a, b) \
    asm("sub.rn.f32x2 %0, %1, %2;" : "=l"(d) : "l"(a), "l"(b))
#define MUL_F32X2(d, a, b) \
    asm("mul.rn.f32x2 %0, %1, %2;" : "=l"(d) : "l"(a), "l"(b))
#define PACK_F32X2(out, lo, hi) \
    asm("mov.b64 %0, {%1, %2};" : "=l"(out) : "f"(lo), "f"(hi))
#define PACK_DUP_F32X2(out, w) \
    asm("mov.b64 %0, {%1, %1};" : "=l"(out) : "r"(__float_as_uint(w)))
#define UNPACK_F32X2(lo, hi, in) \
    asm("mov.b64 {%0, %1}, %2;" : "=f"(lo), "=f"(hi) : "l"(in))

// ---------------- scratch (device globals) ----------------------------------
__device__ float g_feat[67u * NT];     // layer-0 input, channel-major [c][n]
__device__ float g_h0[64u * NT];       // raw h of layer 0
__device__ float g_h1[64u * NT];       // raw h of layer 1
__device__ float g_hmax[128u * 16384]; // per-(bs,o) max of raw h2
__device__ float g_hmin[128u * 16384]; // per-(bs,o) min of raw h2
__device__ float g_sum[3 * 128];
__device__ float g_sqs[3 * 128];

__global__ void zero_stats_kernel() {
    int t = threadIdx.x;
    if (t < 384) { g_sum[t] = 0.f; g_sqs[t] = 0.f; }
}

// ---------------- farthest point sampling ------------------------------------
// One block/batch, 256 thr, 16 pts/thread (8 packed f32x2 pairs).
// Packed distance chain, scalar min/max, deferred index, redux argmax,
// 1 barrier/step. Fewer warps => less barrier skew, 8-entry final stage.
__global__ __launch_bounds__(256, 1)
void fps_kernel(const float* __restrict__ xyz, float* __restrict__ out_newxyz) {
    extern __shared__ float fsm[];
    float* xs = fsm;
    float* ys = fsm + 4096;
    float* zs = fsm + 8192;
    unsigned* rv = (unsigned*)(fsm + 12288);   // [2][8]
    unsigned* ri = (unsigned*)(fsm + 12320);   // [2][8]

    const int b = blockIdx.x, tid = threadIdx.x;
    const int lane = tid & 31, wid = tid >> 5;

    const float* base = xyz + (size_t)b * NN * 3;
    for (int i = tid; i < NN; i += 256) {
        xs[i] = base[i * 3 + 0];
        ys[i] = base[i * 3 + 1];
        zs[i] = base[i * 3 + 2];
    }
    __syncthreads();

    // pack: pair h holds points tid+(2h)*256 (lo) and tid+(2h+1)*256 (hi)
    u64 ppx[8], ppy[8], ppz[8];
    float dist[16];
#pragma unroll
    for (int h = 0; h < 8; h++) {
        int i0 = tid + (2 * h) * 256;
        int i1 = tid + (2 * h + 1) * 256;
        PACK_F32X2(ppx[h], xs[i0], xs[i1]);
        PACK_F32X2(ppy[h], ys[i0], ys[i1]);
        PACK_F32X2(ppz[h], zs[i0], zs[i1]);
        dist[2 * h] = 1e10f; dist[2 * h + 1] = 1e10f;
    }

    int cur = 0;
    for (int s = 0; s < SS; s++) {
        if (tid == 0) {
            float* o = out_newxyz + ((size_t)b * SS + s) * 3;
            o[0] = xs[cur]; o[1] = ys[cur]; o[2] = zs[cur];
        }
        u64 cx2, cy2, cz2;
        PACK_DUP_F32X2(cx2, xs[cur]);
        PACK_DUP_F32X2(cy2, ys[cur]);
        PACK_DUP_F32X2(cz2, zs[cur]);

        // packed mirror of: dx=x-c; d=(dx*dx+dy*dy)+dz*dz; scalar min-update
        float bv = -1.0f;
#pragma unroll
        for (int h = 0; h < 8; h++) {
            u64 dx2, dy2, dz2, m1, m2, s1, m3, d2;
            SUB_F32X2(dx2, ppx[h], cx2);
            SUB_F32X2(dy2, ppy[h], cy2);
            SUB_F32X2(dz2, ppz[h], cz2);
            MUL_F32X2(m1, dx2, dx2);
            MUL_F32X2(m2, dy2, dy2);
            ADD_F32X2(s1, m1, m2);
            MUL_F32X2(m3, dz2, dz2);
            ADD_F32X2(d2, s1, m3);
            float d0, d1;
            UNPACK_F32X2(d0, d1, d2);
            float nd0 = fminf(dist[2 * h], d0);
            float nd1 = fminf(dist[2 * h + 1], d1);
            dist[2 * h] = nd0; dist[2 * h + 1] = nd1;
            bv = fmaxf(bv, fmaxf(nd0, nd1));
        }

        // dist >= 0, so float bits compare monotonically as u32
        unsigned mybits = __float_as_uint(bv);
        unsigned wm = __reduce_max_sync(0xffffffffu, mybits);
        // deferred index: only threads holding the warp max search their 16
        unsigned cand = 0xffffffffu;
        if (mybits == wm) {
#pragma unroll
            for (int t = 15; t >= 0; t--)         // descending: smallest t wins
                if (dist[t] == bv) cand = (unsigned)(tid + t * 256);
        }
        unsigned wi = __reduce_min_sync(0xffffffffu, cand);
        unsigned* rvp = rv + (s & 1) * 8;
        unsigned* rip = ri + (s & 1) * 8;
        if (lane == 0) { rvp[wid] = wm; rip[wid] = wi; }
        __syncthreads();
        // every warp redundantly does the 8-way final argmax (no 2nd barrier)
        unsigned v  = rvp[lane & 7];
        unsigned ix = rip[lane & 7];
        unsigned gm = __reduce_max_sync(0xffffffffu, v);
        unsigned c2 = (v == gm) ? ix : 0xffffffffu;
        cur = (int)__reduce_min_sync(0xffffffffu, c2);
    }
}

// ---------------- ball query + gather + concat -> g_feat ---------------------
// 1024 threads / 32 query-warps per block, 32 blocks per batch.
__global__ __launch_bounds__(1024, 1)
void group_kernel(const float* __restrict__ xyz,
                  const float* __restrict__ points,
                  const float* __restrict__ newxyz) {
    extern __shared__ float gsm[];
    float* xs = gsm;
    float* ys = gsm + 4096;
    float* zs = gsm + 8192;
    float* pn = gsm + 12288;
    int* slots = (int*)(gsm + 16384);       // 32 warps * 32 ints

    const int tid = threadIdx.x;
    const int lane = tid & 31, wid = tid >> 5;
    const int b = blockIdx.x >> 5;          // 32 blocks per batch

    const float* base = xyz + (size_t)b * NN * 3;
    for (int i = tid; i < NN; i += 1024) {
        float x = base[i * 3 + 0], y = base[i * 3 + 1], z = base[i * 3 + 2];
        xs[i] = x; ys[i] = y; zs[i] = z;
        pn[i] = __fadd_rn(__fadd_rn(__fmul_rn(x, x), __fmul_rn(y, y)),
                          __fmul_rn(z, z));
    }
    __syncthreads();

    const int s = (blockIdx.x & 31) * 32 + wid;     // query within batch
    const float* q = newxyz + ((size_t)b * SS + s) * 3;
    const float nx = q[0], ny = q[1], nz = q[2];
    const float qn = __fadd_rn(__fadd_rn(__fmul_rn(nx, nx), __fmul_rn(ny, ny)),
                               __fmul_rn(nz, nz));

    int* msl = slots + wid * 32;
    int cnt = 0;
    for (int c = 0; c < 128 && cnt < 32; c++) {
        int i = c * 32 + lane;
        float dot = __fadd_rn(__fadd_rn(__fmul_rn(nx, xs[i]), __fmul_rn(ny, ys[i])),
                              __fmul_rn(nz, zs[i]));
        float d = __fadd_rn(__fadd_rn(__fmul_rn(-2.0f, dot), qn), pn[i]);
        bool in = !(d > R2);
        unsigned m = __ballot_sync(0xffffffffu, in);
        if (in) {
            int pos = cnt + __popc(m & ((1u << lane) - 1u));
            if (pos < 32) msl[pos] = i;
        }
        cnt += __popc(m);
    }
    __syncwarp();
    int cc = cnt < 32 ? cnt : 32;
    int my = msl[lane < cc ? lane : 0];

    const unsigned n = ((unsigned)(b * SS + s)) * KK + lane;
    g_feat[0u * NT + n] = xs[my] - nx;
    g_feat[1u * NT + n] = ys[my] - ny;
    g_feat[2u * NT + n] = zs[my] - nz;
    const float4* pr = (const float4*)(points + ((size_t)(b * NN + my)) * DD);
#pragma unroll
    for (int j = 0; j < 16; j++) {
        float4 v = pr[j];
        g_feat[(size_t)(3 + 4 * j + 0) * NT + n] = v.x;
        g_feat[(size_t)(3 + 4 * j + 1) * NT + n] = v.y;
        g_feat[(size_t)(3 + 4 * j + 2) * NT + n] = v.z;
        g_feat[(size_t)(3 + 4 * j + 3) * NT + n] = v.w;
    }
}

// ---------------- persistent fused GEMM (R13 exact config) -------------------
// 8x8 microtile, 256 threads, 2 CTAs/SM, float wt + per-iter PACK_DUP;
// stats accumulated in registers, flushed once per CTA.
template <int CIN, int COUT, int NTILE, bool BN, bool LAST>
__global__ __launch_bounds__(256, 2)
void mlp_kernel(const float* __restrict__ in,
                const float* __restrict__ w,
                const float* __restrict__ bias,
                const float* __restrict__ sum_in,
                const float* __restrict__ sqs_in,
                const float* __restrict__ gamma,
                const float* __restrict__ beta,
                float* __restrict__ out,
                float* __restrict__ sum_out,
                float* __restrict__ sqs_out,
                float* __restrict__ hmax,
                float* __restrict__ hmin) {
    constexpr int TNG = NTILE / 8;
    constexpr int NTL = (int)(NT / NTILE);
    extern __shared__ float sm[];
    float* wt  = sm;                        // [CIN][COUT]
    float* xt  = wt + CIN * COUT;           // [CIN][NTILE]
    float* scs = xt + CIN * NTILE;          // [CIN]
    float* shs = scs + CIN;                 // [CIN]

    const int tid = threadIdx.x;
    const int tn = tid % TNG;
    const int to = tid / TNG;

    // ---- once-per-CTA staging ----
    if (BN && tid < CIN) {
        float m = sum_in[tid] * INV_NT;
        float v = sqs_in[tid] * INV_NT - m * m;
        float sc = gamma[tid] / sqrtf(v + BN_EPS);
        scs[tid] = sc;
        shs[tid] = beta[tid] - m * sc;
    }
    for (int i = tid; i < CIN * COUT; i += 256) {
        int o = i / CIN, c = i % CIN;
        wt[c * COUT + o] = w[i];
    }
    float bv8[8];
#pragma unroll
    for (int a = 0; a < 8; a++) bv8[a] = bias[to * 8 + a];

    float s_acc[8], s2_acc[8];
#pragma unroll
    for (int a = 0; a < 8; a++) { s_acc[a] = 0.f; s2_acc[a] = 0.f; }

    // ---- persistent tile loop ----
    for (int tile = blockIdx.x; tile < NTL; tile += MLP_GRID) {
        __syncthreads();   // fence xt reuse (also orders first-tile staging)
        const unsigned nb = (unsigned)tile * (unsigned)NTILE;
        for (int i = tid; i < CIN * NTILE; i += 256) {
            int c = i / NTILE, nn = i % NTILE;
            float v = in[(size_t)c * NT + nb + nn];
            if (BN) v = fmaxf(__fmaf_rn(v, scs[c], shs[c]), 0.0f);
            xt[i] = v;
        }
        __syncthreads();

        u64 acc2[8][4];
#pragma unroll
        for (int a = 0; a < 8; a++)
#pragma unroll
            for (int j = 0; j < 4; j++) acc2[a][j] = 0ull;

#pragma unroll 2
        for (int c = 0; c < CIN; c++) {
            const ulonglong2* xp = (const ulonglong2*)&xt[c * NTILE + tn * 8];
            ulonglong2 x01 = xp[0], x23 = xp[1];
            u64 xr2[4] = {x01.x, x01.y, x23.x, x23.y};
            float4 wa = *(const float4*)&wt[c * COUT + to * 8];
            float4 wb = *(const float4*)&wt[c * COUT + to * 8 + 4];
            float wf[8] = {wa.x, wa.y, wa.z, wa.w, wb.x, wb.y, wb.z, wb.w};
            u64 wp[8];
#pragma unroll
            for (int a = 0; a < 8; a++) PACK_DUP_F32X2(wp[a], wf[a]);
#pragma unroll
            for (int a = 0; a < 8; a++)
#pragma unroll
                for (int j = 0; j < 4; j++)
                    FMA_F32X2(acc2[a][j], wp[a], xr2[j], acc2[a][j]);
        }

        const unsigned n0 = nb + tn * 8;
#pragma unroll
        for (int a = 0; a < 8; a++) {
            int o = to * 8 + a;
            float r[8];
#pragma unroll
            for (int j = 0; j < 4; j++)
                UNPACK_F32X2(r[2 * j], r[2 * j + 1], acc2[a][j]);
            float s = 0.f, s2 = 0.f;
#pragma unroll
            for (int j = 0; j < 8; j++) {
                r[j] = r[j] + bv8[a];
                s += r[j];
                s2 = __fmaf_rn(r[j], r[j], s2);
            }
            s_acc[a] += s;
            s2_acc[a] += s2;
            if (!LAST) {
                float4* op = (float4*)&out[(size_t)o * NT + n0];
                op[0] = make_float4(r[0], r[1], r[2], r[3]);
                op[1] = make_float4(r[4], r[5], r[6], r[7]);
            }
            if (LAST) {
                float mx = r[0], mn = r[0];
#pragma unroll
                for (int j = 1; j < 8; j++) { mx = fmaxf(mx, r[j]); mn = fminf(mn, r[j]); }
                mx = fmaxf(mx, __shfl_xor_sync(0xffffffffu, mx, 1));
                mx = fmaxf(mx, __shfl_xor_sync(0xffffffffu, mx, 2));
                mn = fminf(mn, __shfl_xor_sync(0xffffffffu, mn, 1));
                mn = fminf(mn, __shfl_xor_sync(0xffffffffu, mn, 2));
                if ((tn & 3) == 0) {
                    unsigned bs = nb / KK + (tn >> 2);
                    hmax[(size_t)bs * COUT + o] = mx;
                    hmin[(size_t)bs * COUT + o] = mn;
                }
            }
        }
    }

    // ---- stats flush: once per CTA ----
#pragma unroll
    for (int a = 0; a < 8; a++) {
        float s = s_acc[a], s2 = s2_acc[a];
#pragma unroll
        for (int m = 1; m < TNG; m <<= 1) {
            s  += __shfl_xor_sync(0xffffffffu, s,  m);
            s2 += __shfl_xor_sync(0xffffffffu, s2, m);
        }
        if (tn == 0) {
            atomicAdd(&sum_out[to * 8 + a], s);
            atomicAdd(&sqs_out[to * 8 + a], s2);
        }
    }
}

// ---------------- final BN + ReLU applied to pooled max/min ------------------
__global__ void pool_kernel(const float* __restrict__ hmax,
                            const float* __restrict__ hmin,
                            const float* __restrict__ sum_in,
                            const float* __restrict__ sqs_in,
                            const float* __restrict__ gamma,
                            const float* __restrict__ beta,
                            float* __restrict__ out) {
    unsigned idx = blockIdx.x * 256u + threadIdx.x;
    int o = idx & 127;
    float m = sum_in[o] * INV_NT;
    float v = sqs_in[o] * INV_NT - m * m;
    float sc = gamma[o] / sqrtf(v + BN_EPS);
    float sh = beta[o] - m * sc;
    float r = (sc >= 0.0f) ? hmax[idx] : hmin[idx];
    out[(size_t)BB * SS * 3 + idx] = fmaxf(__fmaf_rn(r, sc, sh), 0.0f);
}

// ---------------- host launch ----------------------------------------------
extern "C" void kernel_launch(void* const* d_in, const int* in_sizes, int n_in,
                              void* d_out, int out_size) {
    const float* xyz    = (const float*)d_in[0];
    const float* points = (const float*)d_in[1];
    const float* w0 = (const float*)d_in[2];
    const float* b0 = (const float*)d_in[3];
    const float* g0 = (const float*)d_in[4];
    const float* be0 = (const float*)d_in[5];
    const float* w1 = (const float*)d_in[6];
    const float* b1 = (const float*)d_in[7];
    const float* g1 = (const float*)d_in[8];
    const float* be1 = (const float*)d_in[9];
    const float* w2 = (const float*)d_in[10];
    const float* b2 = (const float*)d_in[11];
    const float* g2 = (const float*)d_in[12];
    const float* be2 = (const float*)d_in[13];
    float* out = (float*)d_out;

    void *featp, *h0p, *h1p, *hmaxp, *hminp, *sump, *sqsp;
    cudaGetSymbolAddress(&featp, g_feat);
    cudaGetSymbolAddress(&h0p, g_h0);
    cudaGetSymbolAddress(&h1p, g_h1);
    cudaGetSymbolAddress(&hmaxp, g_hmax);
    cudaGetSymbolAddress(&hminp, g_hmin);
    cudaGetSymbolAddress(&sump, g_sum);
    cudaGetSymbolAddress(&sqsp, g_sqs);
    float* sum0 = (float*)sump;        float* sqs0 = (float*)sqsp;
    float* sum1 = sum0 + 128;          float* sqs1 = sqs0 + 128;
    float* sum2 = sum0 + 256;          float* sqs2 = sqs0 + 256;

    const int FPS_SMEM = (12288 + 64) * 4;
    const int GRP_SMEM = (16384 + 1024) * 4;
    const int S1 = (67 * 64 + 67 * 256 + 2 * 67) * 4;
    const int S2 = (64 * 64 + 64 * 256 + 2 * 64) * 4;
    const int S3 = (64 * 128 + 64 * 128 + 2 * 64) * 4;

    cudaFuncSetAttribute(fps_kernel, cudaFuncAttributeMaxDynamicSharedMemorySize, FPS_SMEM);
    cudaFuncSetAttribute(group_kernel, cudaFuncAttributeMaxDynamicSharedMemorySize, GRP_SMEM);
    cudaFuncSetAttribute(mlp_kernel<67, 64, 256, false, false>, cudaFuncAttributeMaxDynamicSharedMemorySize, S1);
    cudaFuncSetAttribute(mlp_kernel<64, 64, 256, true, false>, cudaFuncAttributeMaxDynamicSharedMemorySize, S2);
    cudaFuncSetAttribute(mlp_kernel<64, 128, 128, true, true>, cudaFuncAttributeMaxDynamicSharedMemorySize, S3);

    zero_stats_kernel<<<1, 384>>>();
    fps_kernel<<<BB, 256, FPS_SMEM>>>(xyz, out);
    group_kernel<<<BB * 32, 1024, GRP_SMEM>>>(xyz, points, out);

    mlp_kernel<67, 64, 256, false, false><<<MLP_GRID, 256, S1>>>(
        (const float*)featp, w0, b0, nullptr, nullptr, nullptr, nullptr,
        (float*)h0p, sum0, sqs0, nullptr, nullptr);
    mlp_kernel<64, 64, 256, true, false><<<MLP_GRID, 256, S2>>>(
        (const float*)h0p, w1, b1, sum0, sqs0, g0, be0,
        (float*)h1p, sum1, sqs1, nullptr, nullptr);
    mlp_kernel<64, 128, 128, true, true><<<MLP_GRID, 256, S3>>>(
        (const float*)h1p, w2, b2, sum1, sqs1, g1, be1,
        nullptr, sum2, sqs2, (float*)hmaxp, (float*)hminp);

    pool_kernel<<<(BB * SS * 128) / 256, 256>>>(
        (const float*)hmaxp, (const float*)hminp, sum2, sqs2, g2, be2, out);
}

// round 16
// speedup vs baseline: 1.2027x; 1.1552x over previous
#include <cuda_runtime.h>
#include <cuda_bf16.h>
#include <cstddef>

typedef unsigned long long u64;

// Problem constants
#define BB 16
#define NN 4096
#define DD 64
#define SS 1024          // NPOINT
#define KK 32            // NSAMPLE
#define R2 0.04f         // RADIUS^2
#define NT 524288u       // B*S*K
#define INV_NT (1.0f/524288.0f)
#define BN_EPS 1e-5f
#define MLP_GRID 296     // 2 CTAs/SM * 148 SMs

#define FMA_F32X2(d, a, b, c) \
    asm("fma.rn.f32x2 %0, %1, %2, %3;" : "=l"(d) : "l"(a), "l"(b), "l"(c))
#define ADD_F32X2(d, a, b) \
    asm("add.rn.f32x2 %0, %1, %2;" : "=l"(d) : "l"(a), "l"(b))
#define SUB_F32X2(d, a, b) \
    asm("sub.rn.f32x2 %0, %1, %2;" : "=l"(d) : "l"(a), "l"(b))
#define MUL_F32X2(d, a, b) \
    asm("mul.rn.f32x2 %0, %1, %2;" : "=l"(d) : "l"(a), "l"(b))
#define PACK_F32X2(out, lo, hi) \
    asm("mov.b64 %0, {%1, %2};" : "=l"(out) : "f"(lo), "f"(hi))
#define PACK_DUP_F32X2(out, w) \
    asm("mov.b64 %0, {%1, %1};" : "=l"(out) : "r"(__float_as_uint(w)))
#define UNPACK_F32X2(lo, hi, in) \
    asm("mov.b64 {%0, %1}, %2;" : "=f"(lo), "=f"(hi) : "l"(in))

// ---------------- scratch (device globals) ----------------------------------
__device__ float g_feat[67u * NT];     // layer-0 input, channel-major [c][n]
__device__ float g_h0[64u * NT];       // raw h of layer 0
__device__ float g_h1[64u * NT];       // raw h of layer 1
__device__ float g_hmax[128u * 16384]; // per-(bs,o) max of raw h2
__device__ float g_hmin[128u * 16384]; // per-(bs,o) min of raw h2
__device__ float g_sum[3 * 128];
__device__ float g_sqs[3 * 128];

__global__ void zero_stats_kernel() {
    int t = threadIdx.x;
    if (t < 384) { g_sum[t] = 0.f; g_sqs[t] = 0.f; }
}

// ---------------- farthest point sampling (R15, unchanged) -------------------
__global__ __launch_bounds__(256, 1)
void fps_kernel(const float* __restrict__ xyz, float* __restrict__ out_newxyz) {
    extern __shared__ float fsm[];
    float* xs = fsm;
    float* ys = fsm + 4096;
    float* zs = fsm + 8192;
    unsigned* rv = (unsigned*)(fsm + 12288);   // [2][8]
    unsigned* ri = (unsigned*)(fsm + 12320);   // [2][8]

    const int b = blockIdx.x, tid = threadIdx.x;
    const int lane = tid & 31, wid = tid >> 5;

    const float* base = xyz + (size_t)b * NN * 3;
    for (int i = tid; i < NN; i += 256) {
        xs[i] = base[i * 3 + 0];
        ys[i] = base[i * 3 + 1];
        zs[i] = base[i * 3 + 2];
    }
    __syncthreads();

    u64 ppx[8], ppy[8], ppz[8];
    float dist[16];
#pragma unroll
    for (int h = 0; h < 8; h++) {
        int i0 = tid + (2 * h) * 256;
        int i1 = tid + (2 * h + 1) * 256;
        PACK_F32X2(ppx[h], xs[i0], xs[i1]);
        PACK_F32X2(ppy[h], ys[i0], ys[i1]);
        PACK_F32X2(ppz[h], zs[i0], zs[i1]);
        dist[2 * h] = 1e10f; dist[2 * h + 1] = 1e10f;
    }

    int cur = 0;
    for (int s = 0; s < SS; s++) {
        if (tid == 0) {
            float* o = out_newxyz + ((size_t)b * SS + s) * 3;
            o[0] = xs[cur]; o[1] = ys[cur]; o[2] = zs[cur];
        }
        u64 cx2, cy2, cz2;
        PACK_DUP_F32X2(cx2, xs[cur]);
        PACK_DUP_F32X2(cy2, ys[cur]);
        PACK_DUP_F32X2(cz2, zs[cur]);

        float bv = -1.0f;
#pragma unroll
        for (int h = 0; h < 8; h++) {
            u64 dx2, dy2, dz2, m1, m2, s1, m3, d2;
            SUB_F32X2(dx2, ppx[h], cx2);
            SUB_F32X2(dy2, ppy[h], cy2);
            SUB_F32X2(dz2, ppz[h], cz2);
            MUL_F32X2(m1, dx2, dx2);
            MUL_F32X2(m2, dy2, dy2);
            ADD_F32X2(s1, m1, m2);
            MUL_F32X2(m3, dz2, dz2);
            ADD_F32X2(d2, s1, m3);
            float d0, d1;
            UNPACK_F32X2(d0, d1, d2);
            float nd0 = fminf(dist[2 * h], d0);
            float nd1 = fminf(dist[2 * h + 1], d1);
            dist[2 * h] = nd0; dist[2 * h + 1] = nd1;
            bv = fmaxf(bv, fmaxf(nd0, nd1));
        }

        unsigned mybits = __float_as_uint(bv);
        unsigned wm = __reduce_max_sync(0xffffffffu, mybits);
        unsigned cand = 0xffffffffu;
        if (mybits == wm) {
#pragma unroll
            for (int t = 15; t >= 0; t--)
                if (dist[t] == bv) cand = (unsigned)(tid + t * 256);
        }
        unsigned wi = __reduce_min_sync(0xffffffffu, cand);
        unsigned* rvp = rv + (s & 1) * 8;
        unsigned* rip = ri + (s & 1) * 8;
        if (lane == 0) { rvp[wid] = wm; rip[wid] = wi; }
        __syncthreads();
        unsigned v  = rvp[lane & 7];
        unsigned ix = rip[lane & 7];
        unsigned gm = __reduce_max_sync(0xffffffffu, v);
        unsigned c2 = (v == gm) ? ix : 0xffffffffu;
        cur = (int)__reduce_min_sync(0xffffffffu, c2);
    }
}

// ---------------- ball query + gather + concat (R15, unchanged) --------------
__global__ __launch_bounds__(1024, 1)
void group_kernel(const float* __restrict__ xyz,
                  const float* __restrict__ points,
                  const float* __restrict__ newxyz) {
    extern __shared__ float gsm[];
    float* xs = gsm;
    float* ys = gsm + 4096;
    float* zs = gsm + 8192;
    float* pn = gsm + 12288;
    int* slots = (int*)(gsm + 16384);       // 32 warps * 32 ints

    const int tid = threadIdx.x;
    const int lane = tid & 31, wid = tid >> 5;
    const int b = blockIdx.x >> 5;          // 32 blocks per batch

    const float* base = xyz + (size_t)b * NN * 3;
    for (int i = tid; i < NN; i += 1024) {
        float x = base[i * 3 + 0], y = base[i * 3 + 1], z = base[i * 3 + 2];
        xs[i] = x; ys[i] = y; zs[i] = z;
        pn[i] = __fadd_rn(__fadd_rn(__fmul_rn(x, x), __fmul_rn(y, y)),
                          __fmul_rn(z, z));
    }
    __syncthreads();

    const int s = (blockIdx.x & 31) * 32 + wid;     // query within batch
    const float* q = newxyz + ((size_t)b * SS + s) * 3;
    const float nx = q[0], ny = q[1], nz = q[2];
    const float qn = __fadd_rn(__fadd_rn(__fmul_rn(nx, nx), __fmul_rn(ny, ny)),
                               __fmul_rn(nz, nz));

    int* msl = slots + wid * 32;
    int cnt = 0;
    for (int c = 0; c < 128 && cnt < 32; c++) {
        int i = c * 32 + lane;
        float dot = __fadd_rn(__fadd_rn(__fmul_rn(nx, xs[i]), __fmul_rn(ny, ys[i])),
                              __fmul_rn(nz, zs[i]));
        float d = __fadd_rn(__fadd_rn(__fmul_rn(-2.0f, dot), qn), pn[i]);
        bool in = !(d > R2);
        unsigned m = __ballot_sync(0xffffffffu, in);
        if (in) {
            int pos = cnt + __popc(m & ((1u << lane) - 1u));
            if (pos < 32) msl[pos] = i;
        }
        cnt += __popc(m);
    }
    __syncwarp();
    int cc = cnt < 32 ? cnt : 32;
    int my = msl[lane < cc ? lane : 0];

    const unsigned n = ((unsigned)(b * SS + s)) * KK + lane;
    g_feat[0u * NT + n] = xs[my] - nx;
    g_feat[1u * NT + n] = ys[my] - ny;
    g_feat[2u * NT + n] = zs[my] - nz;
    const float4* pr = (const float4*)(points + ((size_t)(b * NN + my)) * DD);
#pragma unroll
    for (int j = 0; j < 16; j++) {
        float4 v = pr[j];
        g_feat[(size_t)(3 + 4 * j + 0) * NT + n] = v.x;
        g_feat[(size_t)(3 + 4 * j + 1) * NT + n] = v.y;
        g_feat[(size_t)(3 + 4 * j + 2) * NT + n] = v.z;
        g_feat[(size_t)(3 + 4 * j + 3) * NT + n] = v.w;
    }
}

// ---------------- persistent fused GEMM --------------------------------------
// 8x8 microtile, 256 threads, 2 CTAs/SM. float4 x-staging; DESCENDING tile
// order so consumer reads producer's freshest (L2-resident) tiles.
// Stats in registers, flushed once per CTA.
template <int CIN, int COUT, int NTILE, bool BN, bool LAST>
__global__ __launch_bounds__(256, 2)
void mlp_kernel(const float* __restrict__ in,
                const float* __restrict__ w,
                const float* __restrict__ bias,
                const float* __restrict__ sum_in,
                const float* __restrict__ sqs_in,
                const float* __restrict__ gamma,
                const float* __restrict__ beta,
                float* __restrict__ out,
                float* __restrict__ sum_out,
                float* __restrict__ sqs_out,
                float* __restrict__ hmax,
                float* __restrict__ hmin) {
    constexpr int TNG = NTILE / 8;
    constexpr int NTL = (int)(NT / NTILE);
    constexpr int NT4 = NTILE / 4;
    extern __shared__ float sm[];
    float* wt  = sm;                        // [CIN][COUT]
    float* xt  = wt + CIN * COUT;           // [CIN][NTILE]
    float* scs = xt + CIN * NTILE;          // [CIN]
    float* shs = scs + CIN;                 // [CIN]

    const int tid = threadIdx.x;
    const int tn = tid % TNG;
    const int to = tid / TNG;

    // ---- once-per-CTA staging ----
    if (BN && tid < CIN) {
        float m = sum_in[tid] * INV_NT;
        float v = sqs_in[tid] * INV_NT - m * m;
        float sc = gamma[tid] / sqrtf(v + BN_EPS);
        scs[tid] = sc;
        shs[tid] = beta[tid] - m * sc;
    }
    for (int i = tid; i < CIN * COUT; i += 256) {
        int o = i / CIN, c = i % CIN;
        wt[c * COUT + o] = w[i];
    }
    float bv8[8];
#pragma unroll
    for (int a = 0; a < 8; a++) bv8[a] = bias[to * 8 + a];

    float s_acc[8], s2_acc[8];
#pragma unroll
    for (int a = 0; a < 8; a++) { s_acc[a] = 0.f; s2_acc[a] = 0.f; }

    const float4* in4 = (const float4*)in;
    float4* xt4 = (float4*)xt;

    // ---- persistent tile loop (descending for L2 reuse) ----
    for (int tile = NTL - 1 - blockIdx.x; tile >= 0; tile -= MLP_GRID) {
        __syncthreads();   // fence xt reuse (also orders first-tile staging)
        const unsigned nb = (unsigned)tile * (unsigned)NTILE;
        const unsigned nb4 = nb >> 2;
        for (int i = tid; i < CIN * NT4; i += 256) {
            int c = i / NT4, q = i % NT4;
            float4 v = in4[(size_t)c * (NT / 4) + nb4 + q];
            if (BN) {
                float sc = scs[c], sh = shs[c];
                v.x = fmaxf(__fmaf_rn(v.x, sc, sh), 0.0f);
                v.y = fmaxf(__fmaf_rn(v.y, sc, sh), 0.0f);
                v.z = fmaxf(__fmaf_rn(v.z, sc, sh), 0.0f);
                v.w = fmaxf(__fmaf_rn(v.w, sc, sh), 0.0f);
            }
            xt4[i] = v;
        }
        __syncthreads();

        u64 acc2[8][4];
#pragma unroll
        for (int a = 0; a < 8; a++)
#pragma unroll
            for (int j = 0; j < 4; j++) acc2[a][j] = 0ull;

#pragma unroll 2
        for (int c = 0; c < CIN; c++) {
            const ulonglong2* xp = (const ulonglong2*)&xt[c * NTILE + tn * 8];
            ulonglong2 x01 = xp[0], x23 = xp[1];
            u64 xr2[4] = {x01.x, x01.y, x23.x, x23.y};
            float4 wa = *(const float4*)&wt[c * COUT + to * 8];
            float4 wb = *(const float4*)&wt[c * COUT + to * 8 + 4];
            float wf[8] = {wa.x, wa.y, wa.z, wa.w, wb.x, wb.y, wb.z, wb.w};
            u64 wp[8];
#pragma unroll
            for (int a = 0; a < 8; a++) PACK_DUP_F32X2(wp[a], wf[a]);
#pragma unroll
            for (int a = 0; a < 8; a++)
#pragma unroll
                for (int j = 0; j < 4; j++)
                    FMA_F32X2(acc2[a][j], wp[a], xr2[j], acc2[a][j]);
        }

        const unsigned n0 = nb + tn * 8;
#pragma unroll
        for (int a = 0; a < 8; a++) {
            int o = to * 8 + a;
            float r[8];
#pragma unroll
            for (int j = 0; j < 4; j++)
                UNPACK_F32X2(r[2 * j], r[2 * j + 1], acc2[a][j]);
            float s = 0.f, s2 = 0.f;
#pragma unroll
            for (int j = 0; j < 8; j++) {
                r[j] = r[j] + bv8[a];
                s += r[j];
                s2 = __fmaf_rn(r[j], r[j], s2);
            }
            s_acc[a] += s;
            s2_acc[a] += s2;
            if (!LAST) {
                float4* op = (float4*)&out[(size_t)o * NT + n0];
                op[0] = make_float4(r[0], r[1], r[2], r[3]);
                op[1] = make_float4(r[4], r[5], r[6], r[7]);
            }
            if (LAST) {
                float mx = r[0], mn = r[0];
#pragma unroll
                for (int j = 1; j < 8; j++) { mx = fmaxf(mx, r[j]); mn = fminf(mn, r[j]); }
                mx = fmaxf(mx, __shfl_xor_sync(0xffffffffu, mx, 1));
                mx = fmaxf(mx, __shfl_xor_sync(0xffffffffu, mx, 2));
                mn = fminf(mn, __shfl_xor_sync(0xffffffffu, mn, 1));
                mn = fminf(mn, __shfl_xor_sync(0xffffffffu, mn, 2));
                if ((tn & 3) == 0) {
                    unsigned bs = nb / KK + (tn >> 2);
                    hmax[(size_t)bs * COUT + o] = mx;
                    hmin[(size_t)bs * COUT + o] = mn;
                }
            }
        }
    }

    // ---- stats flush: once per CTA ----
#pragma unroll
    for (int a = 0; a < 8; a++) {
        float s = s_acc[a], s2 = s2_acc[a];
#pragma unroll
        for (int m = 1; m < TNG; m <<= 1) {
            s  += __shfl_xor_sync(0xffffffffu, s,  m);
            s2 += __shfl_xor_sync(0xffffffffu, s2, m);
        }
        if (tn == 0) {
            atomicAdd(&sum_out[to * 8 + a], s);
            atomicAdd(&sqs_out[to * 8 + a], s2);
        }
    }
}

// ---------------- final BN + ReLU applied to pooled max/min ------------------
__global__ void pool_kernel(const float* __restrict__ hmax,
                            const float* __restrict__ hmin,
                            const float* __restrict__ sum_in,
                            const float* __restrict__ sqs_in,
                            const float* __restrict__ gamma,
                            const float* __restrict__ beta,
                            float* __restrict__ out) {
    unsigned idx = blockIdx.x * 256u + threadIdx.x;
    int o = idx & 127;
    float m = sum_in[o] * INV_NT;
    float v = sqs_in[o] * INV_NT - m * m;
    float sc = gamma[o] / sqrtf(v + BN_EPS);
    float sh = beta[o] - m * sc;
    float r = (sc >= 0.0f) ? hmax[idx] : hmin[idx];
    out[(size_t)BB * SS * 3 + idx] = fmaxf(__fmaf_rn(r, sc, sh), 0.0f);
}

// ---------------- host launch ----------------------------------------------
extern "C" void kernel_launch(void* const* d_in, const int* in_sizes, int n_in,
                              void* d_out, int out_size) {
    const float* xyz    = (const float*)d_in[0];
    const float* points = (const float*)d_in[1];
    const float* w0 = (const float*)d_in[2];
    const float* b0 = (const float*)d_in[3];
    const float* g0 = (const float*)d_in[4];
    const float* be0 = (const float*)d_in[5];
    const float* w1 = (const float*)d_in[6];
    const float* b1 = (const float*)d_in[7];
    const float* g1 = (const float*)d_in[8];
    const float* be1 = (const float*)d_in[9];
    const float* w2 = (const float*)d_in[10];
    const float* b2 = (const float*)d_in[11];
    const float* g2 = (const float*)d_in[12];
    const float* be2 = (const float*)d_in[13];
    float* out = (float*)d_out;

    void *featp, *h0p, *h1p, *hmaxp, *hminp, *sump, *sqsp;
    cudaGetSymbolAddress(&featp, g_feat);
    cudaGetSymbolAddress(&h0p, g_h0);
    cudaGetSymbolAddress(&h1p, g_h1);
    cudaGetSymbolAddress(&hmaxp, g_hmax);
    cudaGetSymbolAddress(&hminp, g_hmin);
    cudaGetSymbolAddress(&sump, g_sum);
    cudaGetSymbolAddress(&sqsp, g_sqs);
    float* sum0 = (float*)sump;        float* sqs0 = (float*)sqsp;
    float* sum1 = sum0 + 128;          float* sqs1 = sqs0 + 128;
    float* sum2 = sum0 + 256;          float* sqs2 = sqs0 + 256;

    const int FPS_SMEM = (12288 + 64) * 4;
    const int GRP_SMEM = (16384 + 1024) * 4;
    const int S1 = (67 * 64 + 67 * 256 + 2 * 67) * 4;
    const int S2 = (64 * 64 + 64 * 256 + 2 * 64) * 4;
    const int S3 = (64 * 128 + 64 * 128 + 2 * 64) * 4;

    cudaFuncSetAttribute(fps_kernel, cudaFuncAttributeMaxDynamicSharedMemorySize, FPS_SMEM);
    cudaFuncSetAttribute(group_kernel, cudaFuncAttributeMaxDynamicSharedMemorySize, GRP_SMEM);
    cudaFuncSetAttribute(mlp_kernel<67, 64, 256, false, false>, cudaFuncAttributeMaxDynamicSharedMemorySize, S1);
    cudaFuncSetAttribute(mlp_kernel<64, 64, 256, true, false>, cudaFuncAttributeMaxDynamicSharedMemorySize, S2);
    cudaFuncSetAttribute(mlp_kernel<64, 128, 128, true, true>, cudaFuncAttributeMaxDynamicSharedMemorySize, S3);

    zero_stats_kernel<<<1, 384>>>();
    fps_kernel<<<BB, 256, FPS_SMEM>>>(xyz, out);
    group_kernel<<<BB * 32, 1024, GRP_SMEM>>>(xyz, points, out);

    mlp_kernel<67, 64, 256, false, false><<<MLP_GRID, 256, S1>>>(
        (const float*)featp, w0, b0, nullptr, nullptr, nullptr, nullptr,
        (float*)h0p, sum0, sqs0, nullptr, nullptr);
    mlp_kernel<64, 64, 256, true, false><<<MLP_GRID, 256, S2>>>(
        (const float*)h0p, w1, b1, sum0, sqs0, g0, be0,
        (float*)h1p, sum1, sqs1, nullptr, nullptr);
    mlp_kernel<64, 128, 128, true, true><<<MLP_GRID, 256, S3>>>(
        (const float*)h1p, w2, b2, sum1, sqs1, g1, be1,
        nullptr, sum2, sqs2, (float*)hmaxp, (float*)hminp);

    pool_kernel<<<(BB * SS * 128) / 256, 256>>>(
        (const float*)hmaxp, (const float*)hminp, sum2, sqs2, g2, be2, out);
}